// round 8
// baseline (speedup 1.0000x reference)
#include <cuda_runtime.h>

#define BB_ 32
#define HH_ 12
#define CC_ 512
#define DD_ 768
#define EMB_ 768
#define NCLS_ 97
#define KIN_ 1542
#define KCORE_ 1536
#define NB 128

// ---------------- scratch (device globals; no allocation) ----------------
__device__ float g_hs_t[DD_ * BB_];                 // logsumexp head emb [d][b]
__device__ float g_htp[BB_ * CC_];                  // pre-normalized ht_att (b,c)
__device__ float g_htsum[BB_ * 4];                  // 4 partial sums per batch
__device__ float g_rsp[16 * BB_ * DD_];             // rs partials [chunk][b][d]
__device__ float g_rs_t[DD_ * BB_];                 // reduced rs [d][b]
__device__ float g_gp[2 * 16 * EMB_ * BB_];         // GEMM partials [side][ks][n][b]
__device__ float g_hsf_t[EMB_ * BB_];               // tanh head features [n][b]
__device__ float g_tsf_t[EMB_ * BB_];               // tanh tail features [n][b]
__device__ unsigned long long g_lp2[96 * 64 * 32];  // logits partials [ks][P][b]
__device__ unsigned g_cnt[8];                       // barrier counters (reset each use)
__device__ unsigned g_gen[8];                       // barrier generations (monotonic)

// ---------------- helpers ----------------
__device__ __forceinline__ unsigned long long ffma2(unsigned long long a,
                                                    unsigned long long b,
                                                    unsigned long long c) {
    unsigned long long d;
    asm("fma.rn.f32x2 %0, %1, %2, %3;" : "=l"(d) : "l"(a), "l"(b), "l"(c));
    return d;
}
__device__ __forceinline__ unsigned long long pack2(float x) {
    unsigned long long r;
    asm("mov.b64 %0, {%1, %2};" : "=l"(r) : "f"(x), "f"(x));
    return r;
}
__device__ __forceinline__ unsigned long long packxy(float x, float y) {
    unsigned long long r;
    asm("mov.b64 %0, {%1, %2};" : "=l"(r) : "f"(x), "f"(y));
    return r;
}
__device__ __forceinline__ float2 unpack2(unsigned long long v) {
    float2 f;
    asm("mov.b64 {%0, %1}, %2;" : "=f"(f.x), "=f"(f.y) : "l"(v));
    return f;
}
__device__ __forceinline__ float hadd2(unsigned long long v) {
    float2 f = unpack2(v);
    return f.x + f.y;
}
__device__ __forceinline__ void cp_async8(unsigned dst, const void* src) {
    asm volatile("cp.async.ca.shared.global [%0], [%1], 8;\n" :: "r"(dst), "l"(src));
}
__device__ __forceinline__ void wg_bar(int wg) {
    asm volatile("bar.sync %0, %1;" :: "r"(wg + 1), "r"(128) : "memory");
}
__device__ __forceinline__ void prefetch_l2(const void* p) {
    asm volatile("prefetch.global.L2 [%0];" :: "l"(p));
}

// Replay-safe grid barrier: counter resets to 0 every use; generation is
// monotonic (its absolute value never affects computation or output).
__device__ __forceinline__ void grid_bar(int slot) {
    __syncthreads();
    if (threadIdx.x == 0) {
        __threadfence();
        volatile unsigned* genp = &g_gen[slot];
        unsigned my = *genp;
        unsigned old = atomicAdd(&g_cnt[slot], 1u);
        if (old == NB - 1u) {
            g_cnt[slot] = 0u;
            __threadfence();
            atomicAdd(&g_gen[slot], 1u);
        } else {
            while (*genp == my) { __nanosleep(64); }
        }
        __threadfence();
    }
    __syncthreads();
}

// smem layout: 3 warpgroup slots of 37888 B (k3 per-wg: 25600 W + 12288 x2)
#define WG_SLOT 37888
#define SMEM_BYTES (3 * WG_SLOT)

__global__ __launch_bounds__(512, 1) void mega(
    const float* __restrict__ seq, const float* __restrict__ att,
    const float* __restrict__ ner, const float* __restrict__ Wh,
    const float* __restrict__ bh, const float* __restrict__ Wt,
    const float* __restrict__ bt, const float* __restrict__ Wb,
    const float* __restrict__ bbil, const int* __restrict__ ep,
    float* __restrict__ out) {
    extern __shared__ char smem[];
    const int tid = threadIdx.x, bid = blockIdx.x;
    const int wg = tid >> 7, wt = tid & 127;

    // ================= P1: k1 — hs logsumexp + ht_att pre + partial sums ========
    {
        int part = bid & 3, b = bid >> 2;
        int w = tid >> 5, lane = tid & 31;
        int* sp0 = (int*)smem;
        int* sp1 = sp0 + 8;
        float* sacc = (float*)(smem + 64);          // [12][128]
        float* sred = (float*)(smem + 64 + 6144);   // [16]
        if (tid < 16) {
            int side = tid >> 3, m = tid & 7;
            int p = ep[b * 16 + side * 8 + m] + 1;  // OFFSET
            if (side) sp1[m] = p; else sp0[m] = p;
        }
        __syncthreads();

        if (w < 12) {
            const float* ab = att + ((size_t)(b * HH_ + w)) * CC_ * CC_;
            int c4 = part * 128 + lane * 4;
            float4 v0[8], v1[8];
            #pragma unroll
            for (int m = 0; m < 8; m++) {
                v0[m] = *(const float4*)(ab + (size_t)sp0[m] * CC_ + c4);
                v1[m] = *(const float4*)(ab + (size_t)sp1[m] * CC_ + c4);
            }
            float4 a0 = make_float4(0.f, 0.f, 0.f, 0.f);
            float4 a1 = make_float4(0.f, 0.f, 0.f, 0.f);
            #pragma unroll
            for (int m = 0; m < 8; m++) {
                a0.x += v0[m].x; a0.y += v0[m].y; a0.z += v0[m].z; a0.w += v0[m].w;
                a1.x += v1[m].x; a1.y += v1[m].y; a1.z += v1[m].z; a1.w += v1[m].w;
            }
            float4 pr = make_float4(a0.x * a1.x, a0.y * a1.y, a0.z * a1.z, a0.w * a1.w);
            *(float4*)&sacc[w * 128 + lane * 4] = pr;
        }
        __syncthreads();

        float pre = 0.f;
        if (tid < 128) {
            float s = 0.f;
            #pragma unroll
            for (int h = 0; h < 12; h++) s += sacc[h * 128 + tid];
            pre = s * (1.0f / 768.0f);
            g_htp[b * CC_ + part * 128 + tid] = pre;
        }
        #pragma unroll
        for (int o = 16; o > 0; o >>= 1) pre += __shfl_xor_sync(0xffffffffu, pre, o);
        if (lane == 0) sred[w] = pre;
        __syncthreads();
        if (tid == 0)
            g_htsum[b * 4 + part] = sred[0] + sred[1] + sred[2] + sred[3];

        if (part < 2 && tid < 384) {
            int d = part * 384 + tid;
            const float* sb = seq + (size_t)b * CC_ * DD_ + d;
            float v[8];
            #pragma unroll
            for (int m = 0; m < 8; m++) v[m] = sb[(size_t)sp0[m] * DD_];
            float mx = v[0];
            #pragma unroll
            for (int m = 1; m < 8; m++) mx = fmaxf(mx, v[m]);
            float s = 0.f;
            #pragma unroll
            for (int m = 0; m < 8; m++) s += expf(v[m] - mx);
            g_hs_t[d * BB_ + b] = mx + logf(s);
        }
    }
    grid_bar(0);

    // ================= P2: k2 — rs partials (50 MB stream) + L2 weight prefetch ==
    {
        float* sht = (float*)smem;          // [128]
        float* sinvp = sht + 128;
        int b = bid >> 2, sq = bid & 3;
        if (tid == 0) {
            float sm = g_htsum[b * 4] + g_htsum[b * 4 + 1] + g_htsum[b * 4 + 2] + g_htsum[b * 4 + 3];
            sinvp[0] = 1.0f / (sm + 1e-5f);
        }
        if (tid < 128) sht[tid] = g_htp[b * CC_ + sq * 128 + tid];
        __syncthreads();
        if (tid < 384) {
            int g = tid / 192, c = tid - g * 192;
            float sinv = sinvp[0];
            #pragma unroll
            for (int h = 0; h < 2; h++) {
                int j = h * 2 + g;                 // local chunk 0..3
                int chunk = sq * 4 + j;            // global 0..15
                const float4* sp = (const float4*)(seq + ((size_t)b * CC_ + chunk * 32) * DD_) + c;
                float4 acc = make_float4(0.f, 0.f, 0.f, 0.f);
                #pragma unroll
                for (int gg = 0; gg < 4; gg++) {
                    float4 v[8];
                    #pragma unroll
                    for (int u = 0; u < 8; u++) v[u] = sp[(gg * 8 + u) * 192];
                    #pragma unroll
                    for (int u = 0; u < 8; u++) {
                        float wv = sht[j * 32 + gg * 8 + u];
                        acc.x += v[u].x * wv; acc.y += v[u].y * wv;
                        acc.z += v[u].z * wv; acc.w += v[u].w * wv;
                    }
                }
                acc.x *= sinv; acc.y *= sinv; acc.z *= sinv; acc.w *= sinv;
                ((float4*)(g_rsp + ((size_t)chunk * BB_ + b) * DD_))[c] = acc;
            }
        } else {
            // idle threads: prefetch W_head/W_tail/W_bil into L2
            int pid = bid * 128 + (tid - 384);     // 0..16383
            const size_t wbytes = (size_t)DD_ * KIN_ * 4;   // 4.74 MB
            #pragma unroll
            for (int t = 0; t < 3; t++) {
                size_t off = ((size_t)pid + (size_t)t * 16384) * 128;
                if (off < wbytes) {
                    prefetch_l2((const char*)Wh + off);
                    prefetch_l2((const char*)Wt + off);
                }
            }
            const size_t bbytes = (size_t)NCLS_ * 6144 * 4; // 2.38 MB
            #pragma unroll
            for (int t = 0; t < 2; t++) {
                size_t off = ((size_t)pid + (size_t)t * 16384) * 128;
                if (off < bbytes) prefetch_l2((const char*)Wb + off);
            }
        }
    }
    grid_bar(1);

    // ================= P3: k2r — collapse 16 rs partials -> g_rs_t [d][b] =======
    {
        int gid = bid * 512 + tid;
        if (gid < 6144) {
            int b = gid / 192, q = gid - b * 192;
            const float4* src = (const float4*)(g_rsp + (size_t)b * DD_) + q;
            float4 acc = make_float4(0.f, 0.f, 0.f, 0.f);
            #pragma unroll
            for (int g = 0; g < 2; g++) {
                float4 v[8];
                #pragma unroll
                for (int u = 0; u < 8; u++) v[u] = src[(size_t)(g * 8 + u) * BB_ * DD_ / 4];
                #pragma unroll
                for (int u = 0; u < 8; u++) {
                    acc.x += v[u].x; acc.y += v[u].y; acc.z += v[u].z; acc.w += v[u].w;
                }
            }
            int d = q * 4;
            g_rs_t[(d + 0) * BB_ + b] = acc.x;
            g_rs_t[(d + 1) * BB_ + b] = acc.y;
            g_rs_t[(d + 2) * BB_ + b] = acc.z;
            g_rs_t[(d + 3) * BB_ + b] = acc.w;
        }
    }
    grid_bar(2);

    // ================= P4: k3 — dual GEMM, 384 vwgs (3 per CTA), cp.async ========
    if (wg < 3) {
        int vc = bid + 128 * wg;               // 0..383
        int side = vc / 192;
        int rem = vc - side * 192;
        int ks = rem / 12, nt = rem - ks * 12;
        const float* W = side ? Wt : Wh;
        int n0 = nt * 64, k0 = ks * 96;
        int tx = wt & 15, ty = wt >> 4;

        char* slot = smem + wg * WG_SLOT;
        float* w_sf = (float*)slot;                              // [2][64][50]
        unsigned long long* x2 = (unsigned long long*)(slot + 25600); // [48][32]

        #pragma unroll
        for (int ck = 0; ck < 2; ck++) {
            #pragma unroll
            for (int t = 0; t < 12; t++) {
                int idx = wt + t * 128;          // 0..1535
                int n = idx / 24, f2 = idx - n * 24;
                const float* src = W + (size_t)(n0 + n) * KIN_ + k0 + ck * 48 + 2 * f2;
                unsigned dst = (unsigned)__cvta_generic_to_shared(&w_sf[(ck * 64 + n) * 50 + 2 * f2]);
                cp_async8(dst, src);
            }
            asm volatile("cp.async.commit_group;\n" ::: "memory");
        }

        const float* gx = (k0 < 768) ? g_hs_t + (size_t)k0 * BB_
                                     : g_rs_t + (size_t)(k0 - 768) * BB_;
        #pragma unroll
        for (int t = 0; t < 12; t++) {
            int idx = wt + t * 128;              // 0..1535
            int kkp = idx >> 5, b = idx & 31;    // kkp 0..47
            x2[kkp * 32 + b] = packxy(gx[(size_t)(2 * kkp) * BB_ + b],
                                      gx[(size_t)(2 * kkp + 1) * BB_ + b]);
        }

        unsigned long long acc[4][4];
        #pragma unroll
        for (int i = 0; i < 4; i++)
            #pragma unroll
            for (int j = 0; j < 4; j++) acc[i][j] = 0ull;

        asm volatile("cp.async.wait_group 1;\n" ::: "memory");
        wg_bar(wg);

        #pragma unroll
        for (int c = 0; c < 2; c++) {
            #pragma unroll 4
            for (int kkp = 0; kkp < 24; kkp++) {
                unsigned long long w2[4], xb[4];
                #pragma unroll
                for (int i = 0; i < 4; i++)
                    w2[i] = *(const unsigned long long*)&w_sf[(c * 64 + tx + 16 * i) * 50 + 2 * kkp];
                *(ulonglong2*)&xb[0] = *(const ulonglong2*)&x2[(c * 24 + kkp) * 32 + ty * 4];
                *(ulonglong2*)&xb[2] = *(const ulonglong2*)&x2[(c * 24 + kkp) * 32 + ty * 4 + 2];
                #pragma unroll
                for (int i = 0; i < 4; i++)
                    #pragma unroll
                    for (int j = 0; j < 4; j++)
                        acc[i][j] = ffma2(w2[i], xb[j], acc[i][j]);
            }
            if (c == 0) {
                asm volatile("cp.async.wait_group 0;\n" ::: "memory");
                wg_bar(wg);
            }
        }

        float* gp = g_gp + ((size_t)(side * 16 + ks)) * EMB_ * BB_;
        #pragma unroll
        for (int i = 0; i < 4; i++) {
            int n = n0 + tx + 16 * i;
            float4 r;
            r.x = hadd2(acc[i][0]);
            r.y = hadd2(acc[i][1]);
            r.z = hadd2(acc[i][2]);
            r.w = hadd2(acc[i][3]);
            *(float4*)&gp[(size_t)n * BB_ + ty * 4] = r;
        }
    }
    grid_bar(3);

    // ================= P5: k3r — reduce 16 k-partials + NER + bias + tanh ========
    {
        int gid = bid * 512 + tid;
        if (gid < 2 * EMB_ * BB_) {
            int side = gid / (EMB_ * BB_);
            int rem = gid - side * EMB_ * BB_;
            int n = rem >> 5, bb = rem & 31;
            const float* gp = g_gp + (size_t)side * 16 * EMB_ * BB_ + rem;
            float v[16];
            #pragma unroll
            for (int u = 0; u < 16; u++) v[u] = gp[(size_t)u * EMB_ * BB_];
            #pragma unroll
            for (int o = 8; o > 0; o >>= 1)
                #pragma unroll
                for (int u = 0; u < 8; u++)
                    if (u < o) v[u] += v[u + o];
            float s = v[0];
            const float* W = side ? Wt : Wh;
            #pragma unroll
            for (int j = 0; j < 6; j++)
                s += W[(size_t)n * KIN_ + KCORE_ + j] * ner[bb * 12 + side * 6 + j];
            s += (side ? bt : bh)[n];
            float* dst = side ? g_tsf_t : g_hsf_t;
            dst[n * BB_ + bb] = tanhf(s);
        }
    }
    grid_bar(4);

    // ================= P6: k4 — bilinear + logits GEMM partials, 384 vwgs ========
    if (wg < 3) {
        int vc = bid + 128 * wg;               // 0..383
        int nt = vc & 3, ks = vc >> 2;         // nt 0..3, ks 0..95
        int tx = wt & 15, ty = wt >> 4;
        int n0 = nt * 32;

        char* slot = smem + wg * WG_SLOT;
        unsigned long long* x2 = (unsigned long long*)slot;       // [64][32]
        float* w4 = (float*)(slot + 16384);                       // [64][34]
        float* sh = (float*)(slot + 16384 + 8704);                // [8][33]
        float* st = sh + 264;                                     // [8][33]

        #pragma unroll
        for (int t = 0; t < 4; t++) {
            int idx = wt + t * 128;               // 0..511
            int half = idx >> 8;
            int loc = idx & 255;
            int v = loc >> 5, bb = loc & 31;
            float* dstm = half ? st : sh;
            const float* srcm = half ? g_tsf_t : g_hsf_t;
            dstm[v * 33 + bb] = srcm[(ks * 8 + v) * BB_ + bb];
        }
        #pragma unroll
        for (int t = 0; t < 4; t++) {
            int idx = wt + t * 128;               // 0..511
            int n = idx >> 4;
            int kq = idx & 15;
            int nn = n0 + n;
            float4 v = (nn < NCLS_)
                ? *(const float4*)(Wb + (size_t)nn * 6144 + ks * 64 + kq * 4)
                : make_float4(0.f, 0.f, 0.f, 0.f);
            w4[(kq * 4 + 0) * 34 + n] = v.x;
            w4[(kq * 4 + 1) * 34 + n] = v.y;
            w4[(kq * 4 + 2) * 34 + n] = v.z;
            w4[(kq * 4 + 3) * 34 + n] = v.w;
        }
        wg_bar(wg);
        #pragma unroll
        for (int t = 0; t < 16; t++) {
            int idx = wt + t * 128;               // 0..2047
            int kk = idx >> 5, bb = idx & 31;     // kk 0..63
            int i = kk >> 3, j = kk & 7;
            x2[kk * 32 + bb] = pack2(sh[i * 33 + bb] * st[j * 33 + bb]);
        }
        wg_bar(wg);

        unsigned long long acc[4] = {0ull, 0ull, 0ull, 0ull};
        #pragma unroll 4
        for (int kk = 0; kk < 64; kk++) {
            unsigned long long w2 = *(const unsigned long long*)&w4[kk * 34 + 2 * tx];
            #pragma unroll
            for (int j = 0; j < 4; j++)
                acc[j] = ffma2(w2, x2[kk * 32 + ty * 4 + j], acc[j]);
        }
        int P = nt * 16 + tx;
        #pragma unroll
        for (int j = 0; j < 4; j++)
            g_lp2[((size_t)ks * 64 + P) * 32 + ty * 4 + j] = acc[j];
    }
    grid_bar(5);

    // ================= P7: k5 — final reduce + bias -> out ======================
    {
        int gid = bid * 512 + tid;
        if (gid < BB_ * NCLS_) {
            int b = gid / NCLS_, n = gid - b * NCLS_;
            int P = n >> 1, c = n & 1;
            const float* lpf = (const float*)g_lp2;
            float s = bbil[n];
            #pragma unroll
            for (int g = 0; g < 12; g++) {
                float v[8];
                #pragma unroll
                for (int u = 0; u < 8; u++)
                    v[u] = lpf[((((size_t)(g * 8 + u)) * 64 + P) * 32 + b) * 2 + c];
                #pragma unroll
                for (int u = 0; u < 8; u++) s += v[u];
            }
            out[gid] = s;
        }
    }
}

extern "C" void kernel_launch(void* const* d_in, const int* in_sizes, int n_in,
                              void* d_out, int out_size) {
    const float* seq  = (const float*)d_in[0];
    const float* att  = (const float*)d_in[1];
    const float* ner  = (const float*)d_in[2];
    const float* Wh   = (const float*)d_in[3];
    const float* bh   = (const float*)d_in[4];
    const float* Wt   = (const float*)d_in[5];
    const float* bt   = (const float*)d_in[6];
    const float* Wb   = (const float*)d_in[7];
    const float* bbil = (const float*)d_in[8];
    const int*   ep   = (const int*)d_in[9];
    float* out = (float*)d_out;

    cudaFuncSetAttribute(mega, cudaFuncAttributeMaxDynamicSharedMemorySize, SMEM_BYTES);
    mega<<<NB, 512, SMEM_BYTES>>>(seq, att, ner, Wh, bh, Wt, bt, Wb, bbil, ep, out);
}

// round 9
// speedup vs baseline: 1.1901x; 1.1901x over previous
#include <cuda_runtime.h>

#define BB_ 32
#define HH_ 12
#define CC_ 512
#define DD_ 768
#define EMB_ 768
#define NCLS_ 97
#define KIN_ 1542
#define KCORE_ 1536

// ---------------- scratch (device globals; no allocation) ----------------
__device__ float g_hs_t[DD_ * BB_];                     // logsumexp head emb [d][b]
__device__ float g_htp[BB_ * CC_];                      // pre-normalized ht_att (b,c)
__device__ float g_htsum[BB_ * 4];                      // 4 partial sums per batch
__device__ float g_rsp[16 * BB_ * DD_];                 // rs partials [chunk][b][d]
__device__ float g_rs_t[DD_ * BB_];                     // reduced rs [d][b]
__device__ float g_gp[2 * 12 * EMB_ * BB_];             // GEMM partials [side][ks][n][b] scalar
__device__ float g_hsf_t[EMB_ * BB_];                   // tanh head features [n][b]
__device__ float g_tsf_t[EMB_ * BB_];                   // tanh tail features [n][b]
__device__ unsigned long long g_lp2[96 * 64 * 32];      // logits partials [ks][P][b]

// ---------------- f32x2 helpers ----------------
__device__ __forceinline__ unsigned long long ffma2(unsigned long long a,
                                                    unsigned long long b,
                                                    unsigned long long c) {
    unsigned long long d;
    asm("fma.rn.f32x2 %0, %1, %2, %3;" : "=l"(d) : "l"(a), "l"(b), "l"(c));
    return d;
}
__device__ __forceinline__ unsigned long long pack2(float x) {
    unsigned long long r;
    asm("mov.b64 %0, {%1, %2};" : "=l"(r) : "f"(x), "f"(x));
    return r;
}
__device__ __forceinline__ unsigned long long packxy(float x, float y) {
    unsigned long long r;
    asm("mov.b64 %0, {%1, %2};" : "=l"(r) : "f"(x), "f"(y));
    return r;
}
__device__ __forceinline__ float2 unpack2(unsigned long long v) {
    float2 f;
    asm("mov.b64 {%0, %1}, %2;" : "=f"(f.x), "=f"(f.y) : "l"(v));
    return f;
}
__device__ __forceinline__ float hadd2(unsigned long long v) {
    float2 f = unpack2(v);
    return f.x + f.y;
}
__device__ __forceinline__ void cp_async8(unsigned dst, const void* src) {
    asm volatile("cp.async.ca.shared.global [%0], [%1], 8;\n" :: "r"(dst), "l"(src));
}
__device__ __forceinline__ void prefetch_l2(const void* p) {
    asm volatile("prefetch.global.L2 [%0];" :: "l"(p));
}

// ================= K1: hs (logsumexp) + ht_att pre + partial sums =================
__global__ __launch_bounds__(384) void k1(const float* __restrict__ seq,
                                          const float* __restrict__ att,
                                          const int* __restrict__ ep) {
    int part = blockIdx.x, b = blockIdx.y, tid = threadIdx.x;
    int w = tid >> 5, lane = tid & 31;
    __shared__ int sp0[8], sp1[8];
    __shared__ float sacc[12][128];
    __shared__ float sred[12];
    if (tid < 16) {
        int side = tid >> 3, m = tid & 7;
        int p = ep[b * 16 + side * 8 + m] + 1;  // OFFSET
        if (side) sp1[m] = p; else sp0[m] = p;
    }
    __syncthreads();

    {
        const float* ab = att + ((size_t)(b * HH_ + w)) * CC_ * CC_;
        int c4 = part * 128 + lane * 4;
        float4 v0[8], v1[8];
        #pragma unroll
        for (int m = 0; m < 8; m++) {
            v0[m] = *(const float4*)(ab + (size_t)sp0[m] * CC_ + c4);
            v1[m] = *(const float4*)(ab + (size_t)sp1[m] * CC_ + c4);
        }
        float4 a0 = make_float4(0.f, 0.f, 0.f, 0.f);
        float4 a1 = make_float4(0.f, 0.f, 0.f, 0.f);
        #pragma unroll
        for (int m = 0; m < 8; m++) {
            a0.x += v0[m].x; a0.y += v0[m].y; a0.z += v0[m].z; a0.w += v0[m].w;
            a1.x += v1[m].x; a1.y += v1[m].y; a1.z += v1[m].z; a1.w += v1[m].w;
        }
        float4 pr = make_float4(a0.x * a1.x, a0.y * a1.y, a0.z * a1.z, a0.w * a1.w);
        *(float4*)&sacc[w][lane * 4] = pr;
    }
    __syncthreads();

    float pre = 0.f;
    if (tid < 128) {
        float s = 0.f;
        #pragma unroll
        for (int h = 0; h < 12; h++) s += sacc[h][tid];
        pre = s * (1.0f / 768.0f);
        g_htp[b * CC_ + part * 128 + tid] = pre;
    }
    #pragma unroll
    for (int o = 16; o > 0; o >>= 1) pre += __shfl_xor_sync(0xffffffffu, pre, o);
    if (lane == 0) sred[w] = pre;
    __syncthreads();
    if (tid == 0) {
        float s = 0.f;
        #pragma unroll
        for (int i = 0; i < 12; i++) s += sred[i];
        g_htsum[b * 4 + part] = s;
    }

    if (part < 2) {
        int d = part * 384 + tid;
        const float* sb = seq + (size_t)b * CC_ * DD_ + d;
        float v[8];
        #pragma unroll
        for (int m = 0; m < 8; m++) v[m] = sb[(size_t)sp0[m] * DD_];
        float mx = v[0];
        #pragma unroll
        for (int m = 1; m < 8; m++) mx = fmaxf(mx, v[m]);
        float s = 0.f;
        #pragma unroll
        for (int m = 0; m < 8; m++) s += expf(v[m] - mx);
        g_hs_t[d * BB_ + b] = mx + logf(s);
    }
}

// ================= K2: rs partials (50MB stream), MLP=16 + W L2-prefetch =========
__global__ __launch_bounds__(192) void k2(const float* __restrict__ seq,
                                          const float* __restrict__ Wh,
                                          const float* __restrict__ Wt,
                                          const float* __restrict__ Wb) {
    int s = blockIdx.x, b = blockIdx.y, tid = threadIdx.x;
    __shared__ float sht[32];
    __shared__ float sinv;
    if (tid == 0) {
        float sm = g_htsum[b * 4] + g_htsum[b * 4 + 1] + g_htsum[b * 4 + 2] + g_htsum[b * 4 + 3];
        sinv = 1.0f / (sm + 1e-5f);
    }
    if (tid < 32) sht[tid] = g_htp[b * CC_ + s * 32 + tid];

    // L2 prefetch of head/tail/bilinear weights (rides along with the stream)
    {
        size_t gid = (size_t)(b * 16 + s) * 192 + tid;   // 0..98303
        size_t off = gid * 128;
        if (off < (size_t)DD_ * KIN_ * 4) {               // 4.74 MB each
            prefetch_l2((const char*)Wh + off);
            prefetch_l2((const char*)Wt + off);
        }
        if (off < (size_t)NCLS_ * 6144 * 4)               // 2.38 MB
            prefetch_l2((const char*)Wb + off);
    }
    __syncthreads();

    const float4* sp = (const float4*)(seq + ((size_t)b * CC_ + s * 32) * DD_) + tid;
    float4 acc = make_float4(0.f, 0.f, 0.f, 0.f);
    #pragma unroll
    for (int g = 0; g < 2; g++) {
        float4 v[16];
        #pragma unroll
        for (int u = 0; u < 16; u++) v[u] = sp[(g * 16 + u) * 192];   // 16 independent loads
        #pragma unroll
        for (int u = 0; u < 16; u++) {
            float wv = sht[g * 16 + u];
            acc.x += v[u].x * wv; acc.y += v[u].y * wv;
            acc.z += v[u].z * wv; acc.w += v[u].w * wv;
        }
    }
    float iv = sinv;
    acc.x *= iv; acc.y *= iv; acc.z *= iv; acc.w *= iv;
    ((float4*)(g_rsp + ((size_t)s * BB_ + b) * DD_))[tid] = acc;
}

// ================= K2r: collapse 16 rs partials -> g_rs_t [d][b] =================
__global__ __launch_bounds__(256) void k2r() {
    int gid = blockIdx.x * 256 + threadIdx.x;   // 24 * 256 = 6144
    int b = gid / 192, q = gid - b * 192;
    const float4* src = (const float4*)(g_rsp + (size_t)b * DD_) + q;
    float4 acc = make_float4(0.f, 0.f, 0.f, 0.f);
    #pragma unroll
    for (int g = 0; g < 2; g++) {
        float4 v[8];
        #pragma unroll
        for (int u = 0; u < 8; u++) v[u] = src[(size_t)(g * 8 + u) * BB_ * DD_ / 4];
        #pragma unroll
        for (int u = 0; u < 8; u++) {
            acc.x += v[u].x; acc.y += v[u].y; acc.z += v[u].z; acc.w += v[u].w;
        }
    }
    int d = q * 4;
    g_rs_t[(d + 0) * BB_ + b] = acc.x;
    g_rs_t[(d + 1) * BB_ + b] = acc.y;
    g_rs_t[(d + 2) * BB_ + b] = acc.z;
    g_rs_t[(d + 3) * BB_ + b] = acc.w;
}

// ================= K3: dual GEMM, cp.async double-buffered, f32x2 over k-pairs ====
// grid (12, 12, 2): x = n-tile(64), y = k-split(128 = 2 chunks of 64), z = side.
__global__ __launch_bounds__(128) void k3(const float* __restrict__ Wh,
                                          const float* __restrict__ Wt) {
    int nt = blockIdx.x, ks = blockIdx.y, side = blockIdx.z;
    int tid = threadIdx.x, tx = tid & 15, ty = tid >> 4;
    const float* W = side ? Wt : Wh;
    int n0 = nt * 64, k0 = ks * 128;

    __shared__ __align__(16) float w_s[2][64][66];              // [stage][n][k-pair*2]
    __shared__ __align__(16) unsigned long long x2_s[64][32];   // [kkp][b]

    #pragma unroll
    for (int ck = 0; ck < 2; ck++) {
        #pragma unroll
        for (int t = 0; t < 16; t++) {
            int idx = tid + t * 128;          // 0..2047
            int n = idx >> 5, f2 = idx & 31;
            const float* src = W + (size_t)(n0 + n) * KIN_ + k0 + ck * 64 + 2 * f2;
            unsigned dst = (unsigned)__cvta_generic_to_shared(&w_s[ck][n][2 * f2]);
            cp_async8(dst, src);
        }
        asm volatile("cp.async.commit_group;\n" ::: "memory");
    }

    {
        const float* gx = (k0 < 768) ? g_hs_t + (size_t)k0 * BB_
                                     : g_rs_t + (size_t)(k0 - 768) * BB_;
        #pragma unroll
        for (int t = 0; t < 16; t++) {
            int idx = tid + t * 128;
            int kkp = idx >> 5, b = idx & 31;
            float lo = gx[(size_t)(2 * kkp) * BB_ + b];
            float hi = gx[(size_t)(2 * kkp + 1) * BB_ + b];
            x2_s[kkp][b] = packxy(lo, hi);
        }
    }

    unsigned long long acc[4][4];
    #pragma unroll
    for (int i = 0; i < 4; i++)
        #pragma unroll
        for (int j = 0; j < 4; j++) acc[i][j] = 0ull;

    asm volatile("cp.async.wait_group 1;\n" ::: "memory");
    __syncthreads();

    #pragma unroll
    for (int c = 0; c < 2; c++) {
        #pragma unroll 4
        for (int kkp = 0; kkp < 32; kkp++) {
            unsigned long long w2[4], xb[4];
            #pragma unroll
            for (int i = 0; i < 4; i++)
                w2[i] = *(const unsigned long long*)&w_s[c][tx + 16 * i][2 * kkp];
            *(ulonglong2*)&xb[0] = *(const ulonglong2*)&x2_s[c * 32 + kkp][ty * 4];
            *(ulonglong2*)&xb[2] = *(const ulonglong2*)&x2_s[c * 32 + kkp][ty * 4 + 2];
            #pragma unroll
            for (int i = 0; i < 4; i++)
                #pragma unroll
                for (int j = 0; j < 4; j++)
                    acc[i][j] = ffma2(w2[i], xb[j], acc[i][j]);
        }
        if (c == 0) {
            asm volatile("cp.async.wait_group 0;\n" ::: "memory");
            __syncthreads();
        }
    }

    float* gp = g_gp + ((size_t)(side * 12 + ks)) * EMB_ * BB_;
    #pragma unroll
    for (int i = 0; i < 4; i++) {
        int n = n0 + tx + 16 * i;
        float4 r;
        r.x = hadd2(acc[i][0]);
        r.y = hadd2(acc[i][1]);
        r.z = hadd2(acc[i][2]);
        r.w = hadd2(acc[i][3]);
        *(float4*)&gp[(size_t)n * BB_ + ty * 4] = r;
    }
}

// ================= K3r: reduce 12 k-partials + NER + bias + tanh =================
__global__ __launch_bounds__(256) void k3r(const float* __restrict__ Wh,
                                           const float* __restrict__ Wt,
                                           const float* __restrict__ bh,
                                           const float* __restrict__ bt,
                                           const float* __restrict__ ner) {
    int gid = blockIdx.x * 256 + threadIdx.x;
    int side = gid / (EMB_ * BB_);
    int rem = gid - side * EMB_ * BB_;
    int n = rem >> 5, bb = rem & 31;
    const float* gp = g_gp + (size_t)side * 12 * EMB_ * BB_ + rem;
    float v[12];
    #pragma unroll
    for (int u = 0; u < 12; u++) v[u] = gp[(size_t)u * EMB_ * BB_];
    v[0] += v[1]; v[2] += v[3]; v[4] += v[5]; v[6] += v[7]; v[8] += v[9]; v[10] += v[11];
    v[0] += v[2]; v[4] += v[6]; v[8] += v[10];
    float s = v[0] + v[4] + v[8];
    const float* W = side ? Wt : Wh;
    #pragma unroll
    for (int j = 0; j < 6; j++)
        s += W[(size_t)n * KIN_ + KCORE_ + j] * ner[bb * 12 + side * 6 + j];
    s += (side ? bt : bh)[n];
    float* dst = side ? g_tsf_t : g_hsf_t;
    dst[n * BB_ + bb] = tanhf(s);
}

// ================= K4: bilinear + logits GEMM partials, f32x2 =================
__global__ __launch_bounds__(128) void k4(const float* __restrict__ Wb) {
    int nt = blockIdx.x, ks = blockIdx.y;
    int tid = threadIdx.x, tx = tid & 15, ty = tid >> 4;
    int n0 = nt * 32;

    __shared__ float sh[8][33], st[8][33];
    __shared__ float w_s[64][34];
    __shared__ __align__(16) unsigned long long x2_s[64][32];

    #pragma unroll
    for (int t = 0; t < 4; t++) {
        int idx = tid + t * 128;               // 0..511
        int half = idx >> 8;
        int loc = idx & 255;
        int v = loc >> 5, bb = loc & 31;
        float* dstm = half ? &st[0][0] : &sh[0][0];
        const float* srcm = half ? g_tsf_t : g_hsf_t;
        dstm[v * 33 + bb] = srcm[(ks * 8 + v) * BB_ + bb];
    }
    #pragma unroll
    for (int t = 0; t < 4; t++) {
        int idx = tid + t * 128;               // 0..511
        int n = idx >> 4;
        int kq = idx & 15;
        int nn = n0 + n;
        float4 v = (nn < NCLS_)
            ? *(const float4*)(Wb + (size_t)nn * 6144 + ks * 64 + kq * 4)
            : make_float4(0.f, 0.f, 0.f, 0.f);
        w_s[kq * 4 + 0][n] = v.x;
        w_s[kq * 4 + 1][n] = v.y;
        w_s[kq * 4 + 2][n] = v.z;
        w_s[kq * 4 + 3][n] = v.w;
    }
    __syncthreads();
    #pragma unroll
    for (int t = 0; t < 16; t++) {
        int idx = tid + t * 128;               // 0..2047
        int kk = idx >> 5, bb = idx & 31;
        int i = kk >> 3, j = kk & 7;
        x2_s[kk][bb] = pack2(sh[i][bb] * st[j][bb]);
    }
    __syncthreads();

    unsigned long long acc[4] = {0ull, 0ull, 0ull, 0ull};
    #pragma unroll 4
    for (int kk = 0; kk < 64; kk++) {
        unsigned long long w2 = *(const unsigned long long*)&w_s[kk][2 * tx];
        #pragma unroll
        for (int j = 0; j < 4; j++)
            acc[j] = ffma2(w2, x2_s[kk][ty * 4 + j], acc[j]);
    }
    int P = nt * 16 + tx;
    #pragma unroll
    for (int j = 0; j < 4; j++)
        g_lp2[((size_t)ks * 64 + P) * 32 + ty * 4 + j] = acc[j];
}

// ================= K5: final reduce + bias -> d_out =================
__global__ __launch_bounds__(256) void k5(const float* __restrict__ bbil,
                                          float* __restrict__ out) {
    int gid = blockIdx.x * 256 + threadIdx.x;
    if (gid < BB_ * NCLS_) {
        int b = gid / NCLS_, n = gid - b * NCLS_;
        int P = n >> 1, c = n & 1;
        const float* lpf = (const float*)g_lp2;
        float s = bbil[n];
        #pragma unroll
        for (int g = 0; g < 12; g++) {
            float v[8];
            #pragma unroll
            for (int u = 0; u < 8; u++)
                v[u] = lpf[((((size_t)(g * 8 + u)) * 64 + P) * 32 + b) * 2 + c];
            #pragma unroll
            for (int u = 0; u < 8; u++) s += v[u];
        }
        out[gid] = s;
    }
}

extern "C" void kernel_launch(void* const* d_in, const int* in_sizes, int n_in,
                              void* d_out, int out_size) {
    const float* seq  = (const float*)d_in[0];
    const float* att  = (const float*)d_in[1];
    const float* ner  = (const float*)d_in[2];
    const float* Wh   = (const float*)d_in[3];
    const float* bh   = (const float*)d_in[4];
    const float* Wt   = (const float*)d_in[5];
    const float* bt   = (const float*)d_in[6];
    const float* Wb   = (const float*)d_in[7];
    const float* bbil = (const float*)d_in[8];
    const int*   ep   = (const int*)d_in[9];
    float* out = (float*)d_out;

    k1<<<dim3(4, 32), 384>>>(seq, att, ep);
    k2<<<dim3(16, 32), 192>>>(seq, Wh, Wt, Wb);
    k2r<<<24, 256>>>();
    k3<<<dim3(12, 12, 2), 128>>>(Wh, Wt);
    k3r<<<192, 256>>>(Wh, Wt, bh, bt, ner);
    k4<<<dim3(4, 96), 128>>>(Wb);
    k5<<<13, 256>>>(bbil, out);
}

// round 10
// speedup vs baseline: 1.2350x; 1.0378x over previous
#include <cuda_runtime.h>

#define BB_ 32
#define HH_ 12
#define CC_ 512
#define DD_ 768
#define EMB_ 768
#define NCLS_ 97
#define KIN_ 1542
#define KCORE_ 1536

// ---------------- scratch (device globals; no allocation) ----------------
__device__ float g_hs_t[DD_ * BB_];                     // logsumexp head emb [d][b]
__device__ float g_htp[BB_ * CC_];                      // pre-normalized ht_att (b,c)
__device__ float g_htsum[BB_ * 4];                      // 4 partial sums per batch
__device__ float g_rsp[16 * BB_ * DD_];                 // rs partials [chunk][b][d]
__device__ float g_rs_t[DD_ * BB_];                     // reduced rs [d][b]
__device__ float g_gp[2 * 24 * EMB_ * BB_];             // GEMM partials [side][ks][n][b]
__device__ float g_hsf_t[EMB_ * BB_];                   // tanh head features [n][b]
__device__ float g_tsf_t[EMB_ * BB_];                   // tanh tail features [n][b]
__device__ unsigned long long g_lp2[96 * 64 * 32];      // logits partials [ks][P][b]

// ---------------- f32x2 helpers ----------------
__device__ __forceinline__ unsigned long long ffma2(unsigned long long a,
                                                    unsigned long long b,
                                                    unsigned long long c) {
    unsigned long long d;
    asm("fma.rn.f32x2 %0, %1, %2, %3;" : "=l"(d) : "l"(a), "l"(b), "l"(c));
    return d;
}
__device__ __forceinline__ unsigned long long pack2(float x) {
    unsigned long long r;
    asm("mov.b64 %0, {%1, %2};" : "=l"(r) : "f"(x), "f"(x));
    return r;
}
__device__ __forceinline__ unsigned long long packxy(float x, float y) {
    unsigned long long r;
    asm("mov.b64 %0, {%1, %2};" : "=l"(r) : "f"(x), "f"(y));
    return r;
}
__device__ __forceinline__ float2 unpack2(unsigned long long v) {
    float2 f;
    asm("mov.b64 {%0, %1}, %2;" : "=f"(f.x), "=f"(f.y) : "l"(v));
    return f;
}
__device__ __forceinline__ float hadd2(unsigned long long v) {
    float2 f = unpack2(v);
    return f.x + f.y;
}
__device__ __forceinline__ void cp_async8(unsigned dst, const void* src) {
    asm volatile("cp.async.ca.shared.global [%0], [%1], 8;\n" :: "r"(dst), "l"(src));
}

// ================= K1: hs (logsumexp) + ht_att pre + partial sums =================
__global__ __launch_bounds__(384) void k1(const float* __restrict__ seq,
                                          const float* __restrict__ att,
                                          const int* __restrict__ ep) {
    int part = blockIdx.x, b = blockIdx.y, tid = threadIdx.x;
    int w = tid >> 5, lane = tid & 31;
    __shared__ int sp0[8], sp1[8];
    __shared__ float sacc[12][128];
    __shared__ float sred[12];
    if (tid < 16) {
        int side = tid >> 3, m = tid & 7;
        int p = ep[b * 16 + side * 8 + m] + 1;  // OFFSET
        if (side) sp1[m] = p; else sp0[m] = p;
    }
    __syncthreads();

    {
        const float* ab = att + ((size_t)(b * HH_ + w)) * CC_ * CC_;
        int c4 = part * 128 + lane * 4;
        float4 v0[8], v1[8];
        #pragma unroll
        for (int m = 0; m < 8; m++) {
            v0[m] = *(const float4*)(ab + (size_t)sp0[m] * CC_ + c4);
            v1[m] = *(const float4*)(ab + (size_t)sp1[m] * CC_ + c4);
        }
        float4 a0 = make_float4(0.f, 0.f, 0.f, 0.f);
        float4 a1 = make_float4(0.f, 0.f, 0.f, 0.f);
        #pragma unroll
        for (int m = 0; m < 8; m++) {
            a0.x += v0[m].x; a0.y += v0[m].y; a0.z += v0[m].z; a0.w += v0[m].w;
            a1.x += v1[m].x; a1.y += v1[m].y; a1.z += v1[m].z; a1.w += v1[m].w;
        }
        float4 pr = make_float4(a0.x * a1.x, a0.y * a1.y, a0.z * a1.z, a0.w * a1.w);
        *(float4*)&sacc[w][lane * 4] = pr;
    }
    __syncthreads();

    float pre = 0.f;
    if (tid < 128) {
        float s = 0.f;
        #pragma unroll
        for (int h = 0; h < 12; h++) s += sacc[h][tid];
        pre = s * (1.0f / 768.0f);
        g_htp[b * CC_ + part * 128 + tid] = pre;
    }
    #pragma unroll
    for (int o = 16; o > 0; o >>= 1) pre += __shfl_xor_sync(0xffffffffu, pre, o);
    if (lane == 0) sred[w] = pre;
    __syncthreads();
    if (tid == 0) {
        float s = 0.f;
        #pragma unroll
        for (int i = 0; i < 12; i++) s += sred[i];
        g_htsum[b * 4 + part] = s;
    }

    if (part < 2) {
        int d = part * 384 + tid;
        const float* sb = seq + (size_t)b * CC_ * DD_ + d;
        float v[8];
        #pragma unroll
        for (int m = 0; m < 8; m++) v[m] = sb[(size_t)sp0[m] * DD_];
        float mx = v[0];
        #pragma unroll
        for (int m = 1; m < 8; m++) mx = fmaxf(mx, v[m]);
        float s = 0.f;
        #pragma unroll
        for (int m = 0; m < 8; m++) s += expf(v[m] - mx);
        g_hs_t[d * BB_ + b] = mx + logf(s);
    }
}

// ================= K2: rs partials (50MB streaming read), explicit MLP=8 =================
__global__ __launch_bounds__(192) void k2(const float* __restrict__ seq) {
    int s = blockIdx.x, b = blockIdx.y, tid = threadIdx.x;
    __shared__ float sht[32];
    __shared__ float sinv;
    if (tid == 0) {
        float sm = g_htsum[b * 4] + g_htsum[b * 4 + 1] + g_htsum[b * 4 + 2] + g_htsum[b * 4 + 3];
        sinv = 1.0f / (sm + 1e-5f);
    }
    if (tid < 32) sht[tid] = g_htp[b * CC_ + s * 32 + tid];
    __syncthreads();

    const float4* sp = (const float4*)(seq + ((size_t)b * CC_ + s * 32) * DD_) + tid;
    float4 acc = make_float4(0.f, 0.f, 0.f, 0.f);
    #pragma unroll
    for (int g = 0; g < 4; g++) {
        float4 v[8];
        #pragma unroll
        for (int u = 0; u < 8; u++) v[u] = sp[(g * 8 + u) * 192];
        #pragma unroll
        for (int u = 0; u < 8; u++) {
            float wv = sht[g * 8 + u];
            acc.x += v[u].x * wv; acc.y += v[u].y * wv;
            acc.z += v[u].z * wv; acc.w += v[u].w * wv;
        }
    }
    float iv = sinv;
    acc.x *= iv; acc.y *= iv; acc.z *= iv; acc.w *= iv;
    ((float4*)(g_rsp + ((size_t)s * BB_ + b) * DD_))[tid] = acc;
}

// ================= K2r: collapse 16 rs partials -> g_rs_t [d][b] =================
__global__ __launch_bounds__(256) void k2r() {
    int gid = blockIdx.x * 256 + threadIdx.x;   // 24 * 256 = 6144
    int b = gid / 192, q = gid - b * 192;
    const float4* src = (const float4*)(g_rsp + (size_t)b * DD_) + q;
    float4 acc = make_float4(0.f, 0.f, 0.f, 0.f);
    #pragma unroll
    for (int g = 0; g < 2; g++) {
        float4 v[8];
        #pragma unroll
        for (int u = 0; u < 8; u++) v[u] = src[(size_t)(g * 8 + u) * BB_ * DD_ / 4];
        #pragma unroll
        for (int u = 0; u < 8; u++) {
            acc.x += v[u].x; acc.y += v[u].y; acc.z += v[u].z; acc.w += v[u].w;
        }
    }
    int d = q * 4;
    g_rs_t[(d + 0) * BB_ + b] = acc.x;
    g_rs_t[(d + 1) * BB_ + b] = acc.y;
    g_rs_t[(d + 2) * BB_ + b] = acc.z;
    g_rs_t[(d + 3) * BB_ + b] = acc.w;
}

// ================= K3: dual GEMM, 64k per CTA, high residency ====================
// grid (12, 24, 2): x = n-tile(64), y = k-split(64), z = side. 128 threads tx(16)xty(8).
// Thread tile 4 n x 4 b; f32x2 accumulators pair even/odd k. smem 25KB -> ~4 CTAs/SM.
__global__ __launch_bounds__(128) void k3(const float* __restrict__ Wh,
                                          const float* __restrict__ Wt) {
    int nt = blockIdx.x, ks = blockIdx.y, side = blockIdx.z;
    int tid = threadIdx.x, tx = tid & 15, ty = tid >> 4;
    const float* W = side ? Wt : Wh;
    int n0 = nt * 64, k0 = ks * 64;

    __shared__ __align__(16) float w_s[64][66];                 // [n][k-pair*2]
    __shared__ __align__(16) unsigned long long x2_s[32][32];   // [kkp][b]

    // stage W tile 64n x 64k via cp.async (16 x 8B per thread)
    #pragma unroll
    for (int t = 0; t < 16; t++) {
        int idx = tid + t * 128;          // 0..2047
        int n = idx >> 5, f2 = idx & 31;  // f2 = k-pair
        const float* src = W + (size_t)(n0 + n) * KIN_ + k0 + 2 * f2;
        unsigned dst = (unsigned)__cvta_generic_to_shared(&w_s[n][2 * f2]);
        cp_async8(dst, src);
    }
    asm volatile("cp.async.commit_group;\n" ::: "memory");

    // stage x pairs: 32 kkp x 32 b (8 per thread)
    {
        const float* gx = (k0 < 768) ? g_hs_t + (size_t)k0 * BB_
                                     : g_rs_t + (size_t)(k0 - 768) * BB_;
        #pragma unroll
        for (int t = 0; t < 8; t++) {
            int idx = tid + t * 128;          // 0..1023
            int kkp = idx >> 5, b = idx & 31;
            x2_s[kkp][b] = packxy(gx[(size_t)(2 * kkp) * BB_ + b],
                                  gx[(size_t)(2 * kkp + 1) * BB_ + b]);
        }
    }

    unsigned long long acc[4][4];
    #pragma unroll
    for (int i = 0; i < 4; i++)
        #pragma unroll
        for (int j = 0; j < 4; j++) acc[i][j] = 0ull;

    asm volatile("cp.async.wait_group 0;\n" ::: "memory");
    __syncthreads();

    #pragma unroll 4
    for (int kkp = 0; kkp < 32; kkp++) {
        unsigned long long w2[4], xb[4];
        #pragma unroll
        for (int i = 0; i < 4; i++)
            w2[i] = *(const unsigned long long*)&w_s[tx + 16 * i][2 * kkp];
        *(ulonglong2*)&xb[0] = *(const ulonglong2*)&x2_s[kkp][ty * 4];
        *(ulonglong2*)&xb[2] = *(const ulonglong2*)&x2_s[kkp][ty * 4 + 2];
        #pragma unroll
        for (int i = 0; i < 4; i++)
            #pragma unroll
            for (int j = 0; j < 4; j++)
                acc[i][j] = ffma2(w2[i], xb[j], acc[i][j]);
    }

    // epilogue: horizontal add (even+odd k), float4 stores
    float* gp = g_gp + ((size_t)(side * 24 + ks)) * EMB_ * BB_;
    #pragma unroll
    for (int i = 0; i < 4; i++) {
        int n = n0 + tx + 16 * i;
        float4 r;
        r.x = hadd2(acc[i][0]);
        r.y = hadd2(acc[i][1]);
        r.z = hadd2(acc[i][2]);
        r.w = hadd2(acc[i][3]);
        *(float4*)&gp[(size_t)n * BB_ + ty * 4] = r;
    }
}

// ================= K3r: reduce 24 k-partials (MLP=8 batches) + NER + bias + tanh ==
__global__ __launch_bounds__(256) void k3r(const float* __restrict__ Wh,
                                           const float* __restrict__ Wt,
                                           const float* __restrict__ bh,
                                           const float* __restrict__ bt,
                                           const float* __restrict__ ner) {
    int gid = blockIdx.x * 256 + threadIdx.x;
    int side = gid / (EMB_ * BB_);
    int rem = gid - side * EMB_ * BB_;
    int n = rem >> 5, bb = rem & 31;
    const float* gp = g_gp + (size_t)side * 24 * EMB_ * BB_ + rem;
    float s = 0.f;
    #pragma unroll
    for (int g = 0; g < 3; g++) {
        float v[8];
        #pragma unroll
        for (int u = 0; u < 8; u++) v[u] = gp[(size_t)(g * 8 + u) * EMB_ * BB_];
        v[0] += v[1]; v[2] += v[3]; v[4] += v[5]; v[6] += v[7];
        v[0] += v[2]; v[4] += v[6];
        s += v[0] + v[4];
    }
    const float* W = side ? Wt : Wh;
    #pragma unroll
    for (int j = 0; j < 6; j++)
        s += W[(size_t)n * KIN_ + KCORE_ + j] * ner[bb * 12 + side * 6 + j];
    s += (side ? bt : bh)[n];
    float* dst = side ? g_tsf_t : g_hsf_t;
    dst[n * BB_ + bb] = tanhf(s);
}

// ================= K4: bilinear + logits GEMM partials, f32x2 =================
__global__ __launch_bounds__(128) void k4(const float* __restrict__ Wb) {
    int nt = blockIdx.x, ks = blockIdx.y;
    int tid = threadIdx.x, tx = tid & 15, ty = tid >> 4;
    int n0 = nt * 32;

    __shared__ float sh[8][33], st[8][33];
    __shared__ float w_s[64][34];
    __shared__ __align__(16) unsigned long long x2_s[64][32];

    #pragma unroll
    for (int t = 0; t < 4; t++) {
        int idx = tid + t * 128;               // 0..511
        int half = idx >> 8;
        int loc = idx & 255;
        int v = loc >> 5, bb = loc & 31;
        float* dstm = half ? &st[0][0] : &sh[0][0];
        const float* srcm = half ? g_tsf_t : g_hsf_t;
        dstm[v * 33 + bb] = srcm[(ks * 8 + v) * BB_ + bb];
    }
    #pragma unroll
    for (int t = 0; t < 4; t++) {
        int idx = tid + t * 128;               // 0..511
        int n = idx >> 4;
        int kq = idx & 15;
        int nn = n0 + n;
        float4 v = (nn < NCLS_)
            ? *(const float4*)(Wb + (size_t)nn * 6144 + ks * 64 + kq * 4)
            : make_float4(0.f, 0.f, 0.f, 0.f);
        w_s[kq * 4 + 0][n] = v.x;
        w_s[kq * 4 + 1][n] = v.y;
        w_s[kq * 4 + 2][n] = v.z;
        w_s[kq * 4 + 3][n] = v.w;
    }
    __syncthreads();
    #pragma unroll
    for (int t = 0; t < 16; t++) {
        int idx = tid + t * 128;               // 0..2047
        int kk = idx >> 5, bb = idx & 31;
        int i = kk >> 3, j = kk & 7;
        x2_s[kk][bb] = pack2(sh[i][bb] * st[j][bb]);
    }
    __syncthreads();

    unsigned long long acc[4] = {0ull, 0ull, 0ull, 0ull};
    #pragma unroll 4
    for (int kk = 0; kk < 64; kk++) {
        unsigned long long w2 = *(const unsigned long long*)&w_s[kk][2 * tx];
        #pragma unroll
        for (int j = 0; j < 4; j++)
            acc[j] = ffma2(w2, x2_s[kk][ty * 4 + j], acc[j]);
    }
    int P = nt * 16 + tx;
    #pragma unroll
    for (int j = 0; j < 4; j++)
        g_lp2[((size_t)ks * 64 + P) * 32 + ty * 4 + j] = acc[j];
}

// ================= K5: final reduce + bias -> d_out =================
__global__ __launch_bounds__(256) void k5(const float* __restrict__ bbil,
                                          float* __restrict__ out) {
    int gid = blockIdx.x * 256 + threadIdx.x;
    if (gid < BB_ * NCLS_) {
        int b = gid / NCLS_, n = gid - b * NCLS_;
        int P = n >> 1, c = n & 1;
        const float* lpf = (const float*)g_lp2;
        float s = bbil[n];
        #pragma unroll
        for (int g = 0; g < 12; g++) {
            float v[8];
            #pragma unroll
            for (int u = 0; u < 8; u++)
                v[u] = lpf[((((size_t)(g * 8 + u)) * 64 + P) * 32 + b) * 2 + c];
            #pragma unroll
            for (int u = 0; u < 8; u++) s += v[u];
        }
        out[gid] = s;
    }
}

extern "C" void kernel_launch(void* const* d_in, const int* in_sizes, int n_in,
                              void* d_out, int out_size) {
    const float* seq  = (const float*)d_in[0];
    const float* att  = (const float*)d_in[1];
    const float* ner  = (const float*)d_in[2];
    const float* Wh   = (const float*)d_in[3];
    const float* bh   = (const float*)d_in[4];
    const float* Wt   = (const float*)d_in[5];
    const float* bt   = (const float*)d_in[6];
    const float* Wb   = (const float*)d_in[7];
    const float* bbil = (const float*)d_in[8];
    const int*   ep   = (const int*)d_in[9];
    float* out = (float*)d_out;

    k1<<<dim3(4, 32), 384>>>(seq, att, ep);
    k2<<<dim3(16, 32), 192>>>(seq);
    k2r<<<24, 256>>>();
    k3<<<dim3(12, 24, 2), 128>>>(Wh, Wt);
    k3r<<<192, 256>>>(Wh, Wt, bh, bt, ner);
    k4<<<dim3(4, 96), 128>>>(Wb);
    k5<<<13, 256>>>(bbil, out);
}